// round 14
// baseline (speedup 1.0000x reference)
#include <cuda_runtime.h>
#include <cuda_bf16.h>

// HANMeta: B=512, P=64, K=8, D=512, T=50000
// Two-phase L2 working-set separation, warp-per-row, cp.async gathers both phases.
// Phase 1: dots + softmax + focal copy; neighbor gathers via cp.async -> smem.
// Phase 2: weighted title aggregation; title gathers via cp.async -> smem.

#define HM_B 512
#define HM_P 64
#define HM_K 8
#define HM_D 512
#define HM_D4 (HM_D / 4)            // 128 float4 per row
#define HM_ROWS (HM_B * HM_P)       // 32768
#define HM_CHUNKS 4
#define FULL 0xffffffffu

// Per-(row,k) softmax weights scratch: 1 MB.
__device__ float g_w[HM_ROWS * HM_K];

// ---------------- Phase 1: dots + softmax + focal copy (inputs only) --------
__global__ __launch_bounds__(256, 6) void han_attn_kernel(
    const float* __restrict__ inputs,
    const int*   __restrict__ nbr_batch,
    const int*   __restrict__ nbr_job,
    const int*   __restrict__ nbr_mask,
    float*       __restrict__ out)
{
    // [warp][k][lane] float4: 8*8*32*16 = 32 KB.
    __shared__ float4 s_nbr[8][HM_K][32];

    const int warp = threadIdx.x >> 5;
    const int lane = threadIdx.x & 31;
    const int row  = blockIdx.x * 8 + warp;

    // Lanes 0..7 load indices; mask folded into offset sentinel (-1 = masked).
    int off_l = -1;
    if (lane < HM_K) {
        const int base = row * HM_K + lane;
        const int o = (nbr_batch[base] * HM_P + nbr_job[base]) * HM_D4;
        off_l = nbr_mask[base] ? o : -1;
    }
    int off[HM_K];
    #pragma unroll
    for (int k = 0; k < HM_K; k++)
        off[k] = __shfl_sync(FULL, off_l, k);

    const float4* in4 = reinterpret_cast<const float4*>(inputs);
    float4* o4 = reinterpret_cast<float4*>(out) + (long long)row * (2 * HM_D4);

    // All 4 focal loads issued up-front (independent, front-batched).
    const int fbase = row * HM_D4 + lane;
    float4 fv[HM_CHUNKS];
    #pragma unroll
    for (int c = 0; c < HM_CHUNKS; c++)
        fv[c] = __ldcg(&in4[fbase + c * 32]);

    // Neighbor gathers via cp.async: 8 copies in flight per chunk, no data regs.
    float part[HM_K] = {0.f, 0.f, 0.f, 0.f, 0.f, 0.f, 0.f, 0.f};
    #pragma unroll
    for (int c = 0; c < HM_CHUNKS; c++) {
        const int col = c * 32 + lane;
        #pragma unroll
        for (int k = 0; k < HM_K; k++) {
            if (off[k] >= 0) {
                const unsigned s_addr =
                    (unsigned)__cvta_generic_to_shared(&s_nbr[warp][k][lane]);
                asm volatile(
                    "cp.async.cg.shared.global [%0], [%1], 16;\n"
                    :: "r"(s_addr), "l"(&in4[off[k] + col]) : "memory");
            }
        }
        asm volatile("cp.async.commit_group;\n" ::: "memory");
        asm volatile("cp.async.wait_group 0;\n" ::: "memory");
        // Each lane reads back only its own copied slot -> no syncwarp needed.
        #pragma unroll
        for (int k = 0; k < HM_K; k++) {
            if (off[k] >= 0) {
                const float4 nv = s_nbr[warp][k][lane];
                part[k] = fmaf(fv[c].x, nv.x,
                          fmaf(fv[c].y, nv.y,
                          fmaf(fv[c].z, nv.z,
                          fmaf(fv[c].w, nv.w, part[k]))));
            }
        }
    }

    // Focal half of output, after the gather loop.
    #pragma unroll
    for (int c = 0; c < HM_CHUNKS; c++)
        __stcs(&o4[c * 32 + lane], fv[c]);

    #pragma unroll
    for (int sh = 16; sh > 0; sh >>= 1) {
        #pragma unroll
        for (int k = 0; k < HM_K; k++)
            part[k] += __shfl_xor_sync(FULL, part[k], sh);
    }

    // Softmax (redundant per lane; mirrors reference incl. all-masked -> 0 row).
    float logit[HM_K], w[HM_K];
    float m = -3.0e38f;
    #pragma unroll
    for (int k = 0; k < HM_K; k++) {
        logit[k] = (off[k] >= 0) ? part[k] : -1e9f;
        m = fmaxf(m, logit[k]);
    }
    float sum = 0.0f;
    #pragma unroll
    for (int k = 0; k < HM_K; k++) {
        w[k] = __expf(logit[k] - m);
        sum += w[k];
    }
    const float inv = 1.0f / sum;
    #pragma unroll
    for (int k = 0; k < HM_K; k++)
        w[k] = (off[k] >= 0) ? (w[k] * inv) : 0.0f;

    if (lane < HM_K)
        __stcs(&g_w[row * HM_K + lane], w[lane]);
}

// ------- Phase 2: weighted title aggregation, cp.async gathers (R13) --------
__global__ __launch_bounds__(256, 6) void han_aggr_kernel(
    const float* __restrict__ title,
    const int*   __restrict__ nbr_title,
    float*       __restrict__ out)
{
    // [warp][k][lane] float4: 8*8*32*16 = 32 KB.
    __shared__ float4 s_tile[8][HM_K][32];

    const int warp = threadIdx.x >> 5;
    const int lane = threadIdx.x & 31;
    const int row  = blockIdx.x * 8 + warp;

    float w_l = 0.0f; int nt_l = 0;
    if (lane < HM_K) {
        const int base = row * HM_K + lane;
        w_l  = __ldcs(&g_w[base]);
        nt_l = nbr_title[base] << 7;     // *HM_D4, float4 units
    }
    float w[HM_K]; int nt[HM_K];
    #pragma unroll
    for (int k = 0; k < HM_K; k++) {
        w[k]  = __shfl_sync(FULL, w_l, k);
        nt[k] = __shfl_sync(FULL, nt_l, k);
    }

    const float4* t4 = reinterpret_cast<const float4*>(title);
    float4* o4 = reinterpret_cast<float4*>(out)
               + (long long)row * (2 * HM_D4) + HM_D4;

    #pragma unroll
    for (int c = 0; c < HM_CHUNKS; c++) {
        const int col = c * 32 + lane;
        // Issue up to 8 async 16B copies; masked (w==0, warp-uniform) skipped.
        #pragma unroll
        for (int k = 0; k < HM_K; k++) {
            if (w[k] != 0.0f) {
                const unsigned s_addr =
                    (unsigned)__cvta_generic_to_shared(&s_tile[warp][k][lane]);
                asm volatile(
                    "cp.async.cg.shared.global [%0], [%1], 16;\n"
                    :: "r"(s_addr), "l"(&t4[nt[k] + col]) : "memory");
            }
        }
        asm volatile("cp.async.commit_group;\n" ::: "memory");
        asm volatile("cp.async.wait_group 0;\n" ::: "memory");
        // Each lane reads back only its own copied slot -> no syncwarp needed.
        float4 acc = make_float4(0.f, 0.f, 0.f, 0.f);
        #pragma unroll
        for (int k = 0; k < HM_K; k++) {
            if (w[k] != 0.0f) {
                const float4 tv = s_tile[warp][k][lane];
                acc.x = fmaf(w[k], tv.x, acc.x);
                acc.y = fmaf(w[k], tv.y, acc.y);
                acc.z = fmaf(w[k], tv.z, acc.z);
                acc.w = fmaf(w[k], tv.w, acc.w);
            }
        }
        __stcs(&o4[col], acc);
    }
}

extern "C" void kernel_launch(void* const* d_in, const int* in_sizes, int n_in,
                              void* d_out, int out_size)
{
    const float* inputs    = (const float*)d_in[0];
    const float* title     = (const float*)d_in[1];
    const int*   nbr_batch = (const int*)  d_in[2];
    const int*   nbr_job   = (const int*)  d_in[3];
    const int*   nbr_title = (const int*)  d_in[4];
    const int*   nbr_mask  = (const int*)  d_in[5];
    float*       out       = (float*)d_out;

    han_attn_kernel<<<HM_ROWS / 8, 256>>>(inputs, nbr_batch, nbr_job, nbr_mask, out);
    han_aggr_kernel<<<HM_ROWS / 8, 256>>>(title, nbr_title, out);
}

// round 15
// speedup vs baseline: 1.0519x; 1.0519x over previous
#include <cuda_runtime.h>
#include <cuda_bf16.h>

// HANMeta: B=512, P=64, K=8, D=512, T=50000
// Two-phase L2 working-set separation, warp-per-row. (Best-measured config, R13.)
// Phase 1: register-batched gathers (L2-hit dominated; ptxas pipeline suffices).
// Phase 2: cp.async gathers into smem (DRAM-miss dominated; MLP without regs).

#define HM_B 512
#define HM_P 64
#define HM_K 8
#define HM_D 512
#define HM_D4 (HM_D / 4)            // 128 float4 per row
#define HM_ROWS (HM_B * HM_P)       // 32768
#define HM_CHUNKS 4
#define FULL 0xffffffffu

// Per-(row,k) softmax weights scratch: 1 MB.
__device__ float g_w[HM_ROWS * HM_K];

// ---------------- Phase 1: dots + softmax + focal copy (inputs only) --------
__global__ __launch_bounds__(256, 4) void han_attn_kernel(
    const float* __restrict__ inputs,
    const int*   __restrict__ nbr_batch,
    const int*   __restrict__ nbr_job,
    const int*   __restrict__ nbr_mask,
    float*       __restrict__ out)
{
    const int warp = threadIdx.x >> 5;
    const int lane = threadIdx.x & 31;
    const int row  = blockIdx.x * 8 + warp;

    // Lanes 0..7 load indices; mask folded into offset sentinel (-1 = masked).
    int off_l = -1;
    if (lane < HM_K) {
        const int base = row * HM_K + lane;
        const int o = (nbr_batch[base] * HM_P + nbr_job[base]) * HM_D4;
        off_l = nbr_mask[base] ? o : -1;
    }
    int off[HM_K];
    #pragma unroll
    for (int k = 0; k < HM_K; k++)
        off[k] = __shfl_sync(FULL, off_l, k);

    const float4* in4 = reinterpret_cast<const float4*>(inputs);
    float4* o4 = reinterpret_cast<float4*>(out) + (long long)row * (2 * HM_D4);

    // All 4 focal loads issued up-front (independent, front-batched).
    const int fbase = row * HM_D4 + lane;
    float4 fv[HM_CHUNKS];
    #pragma unroll
    for (int c = 0; c < HM_CHUNKS; c++)
        fv[c] = __ldcg(&in4[fbase + c * 32]);

    // Gathers: 8 per chunk, no stores interleaved -> long clean load window.
    float part[HM_K] = {0.f, 0.f, 0.f, 0.f, 0.f, 0.f, 0.f, 0.f};
    #pragma unroll
    for (int c = 0; c < HM_CHUNKS; c++) {
        #pragma unroll
        for (int k = 0; k < HM_K; k++) {
            if (off[k] >= 0) {
                const float4 nv = __ldcg(&in4[off[k] + c * 32 + lane]);
                part[k] = fmaf(fv[c].x, nv.x,
                          fmaf(fv[c].y, nv.y,
                          fmaf(fv[c].z, nv.z,
                          fmaf(fv[c].w, nv.w, part[k]))));
            }
        }
    }

    // Focal half of output, after the load batch.
    #pragma unroll
    for (int c = 0; c < HM_CHUNKS; c++)
        __stcs(&o4[c * 32 + lane], fv[c]);

    #pragma unroll
    for (int sh = 16; sh > 0; sh >>= 1) {
        #pragma unroll
        for (int k = 0; k < HM_K; k++)
            part[k] += __shfl_xor_sync(FULL, part[k], sh);
    }

    // Softmax (redundant per lane; mirrors reference incl. all-masked -> 0 row).
    float logit[HM_K], w[HM_K];
    float m = -3.0e38f;
    #pragma unroll
    for (int k = 0; k < HM_K; k++) {
        logit[k] = (off[k] >= 0) ? part[k] : -1e9f;
        m = fmaxf(m, logit[k]);
    }
    float sum = 0.0f;
    #pragma unroll
    for (int k = 0; k < HM_K; k++) {
        w[k] = __expf(logit[k] - m);
        sum += w[k];
    }
    const float inv = 1.0f / sum;
    #pragma unroll
    for (int k = 0; k < HM_K; k++)
        w[k] = (off[k] >= 0) ? (w[k] * inv) : 0.0f;

    if (lane < HM_K)
        __stcs(&g_w[row * HM_K + lane], w[lane]);
}

// ------- Phase 2: weighted title aggregation, cp.async gathers --------------
__global__ __launch_bounds__(256, 6) void han_aggr_kernel(
    const float* __restrict__ title,
    const int*   __restrict__ nbr_title,
    float*       __restrict__ out)
{
    // [warp][k][lane] float4: 8*8*32*16 = 32 KB.
    __shared__ float4 s_tile[8][HM_K][32];

    const int warp = threadIdx.x >> 5;
    const int lane = threadIdx.x & 31;
    const int row  = blockIdx.x * 8 + warp;

    float w_l = 0.0f; int nt_l = 0;
    if (lane < HM_K) {
        const int base = row * HM_K + lane;
        w_l  = __ldcs(&g_w[base]);
        nt_l = nbr_title[base] << 7;     // *HM_D4, float4 units
    }
    float w[HM_K]; int nt[HM_K];
    #pragma unroll
    for (int k = 0; k < HM_K; k++) {
        w[k]  = __shfl_sync(FULL, w_l, k);
        nt[k] = __shfl_sync(FULL, nt_l, k);
    }

    const float4* t4 = reinterpret_cast<const float4*>(title);
    float4* o4 = reinterpret_cast<float4*>(out)
               + (long long)row * (2 * HM_D4) + HM_D4;

    #pragma unroll
    for (int c = 0; c < HM_CHUNKS; c++) {
        const int col = c * 32 + lane;
        // Issue up to 8 async 16B copies; masked (w==0, warp-uniform) skipped.
        #pragma unroll
        for (int k = 0; k < HM_K; k++) {
            if (w[k] != 0.0f) {
                const unsigned s_addr =
                    (unsigned)__cvta_generic_to_shared(&s_tile[warp][k][lane]);
                asm volatile(
                    "cp.async.cg.shared.global [%0], [%1], 16;\n"
                    :: "r"(s_addr), "l"(&t4[nt[k] + col]) : "memory");
            }
        }
        asm volatile("cp.async.commit_group;\n" ::: "memory");
        asm volatile("cp.async.wait_group 0;\n" ::: "memory");
        // Each lane reads back only its own copied slot -> no syncwarp needed.
        float4 acc = make_float4(0.f, 0.f, 0.f, 0.f);
        #pragma unroll
        for (int k = 0; k < HM_K; k++) {
            if (w[k] != 0.0f) {
                const float4 tv = s_tile[warp][k][lane];
                acc.x = fmaf(w[k], tv.x, acc.x);
                acc.y = fmaf(w[k], tv.y, acc.y);
                acc.z = fmaf(w[k], tv.z, acc.z);
                acc.w = fmaf(w[k], tv.w, acc.w);
            }
        }
        __stcs(&o4[col], acc);
    }
}

extern "C" void kernel_launch(void* const* d_in, const int* in_sizes, int n_in,
                              void* d_out, int out_size)
{
    const float* inputs    = (const float*)d_in[0];
    const float* title     = (const float*)d_in[1];
    const int*   nbr_batch = (const int*)  d_in[2];
    const int*   nbr_job   = (const int*)  d_in[3];
    const int*   nbr_title = (const int*)  d_in[4];
    const int*   nbr_mask  = (const int*)  d_in[5];
    float*       out       = (float*)d_out;

    han_attn_kernel<<<HM_ROWS / 8, 256>>>(inputs, nbr_batch, nbr_job, nbr_mask, out);
    han_aggr_kernel<<<HM_ROWS / 8, 256>>>(title, nbr_title, out);
}